// round 1
// baseline (speedup 1.0000x reference)
#include <cuda_runtime.h>
#include <cuda_bf16.h>

// ---------------------------------------------------------------------------
// MaterialPropertyPredictor: only feat[0:64] is live (winner indexes 0..63),
// so the 500K-row MLP collapses to 64 rows. Pipeline:
//   K1: per-row MLP for rows 0..63 -> g_feat ; winner[] ; transpose Wn1/Wn2
//   K2: grid_feats gather -> relu(@Wn1+bn1) -> @Wn2+bn2 -> g_y (row-local)
//   K3: agg = mean_g(y) ; heads ; write 4 floats
// ---------------------------------------------------------------------------

#define G 64

__device__ float g_feat[G * 256];
__device__ int   g_winner[G];
__device__ float g_Wn1T[256 * 256];
__device__ float g_Wn2T[256 * 256];
__device__ float g_y[G * 256];

__global__ void k_prep(const float* __restrict__ pos, const float* __restrict__ gp,
                       const float* __restrict__ W1, const float* __restrict__ b1,
                       const float* __restrict__ W2, const float* __restrict__ b2,
                       const float* __restrict__ W3, const float* __restrict__ b3,
                       const float* __restrict__ Wn1, const float* __restrict__ Wn2)
{
    const int b = blockIdx.x;
    const int t = threadIdx.x;

    if (b < G) {
        // Per-position MLP: 3 -> 64 -> 128 -> 256 for row b
        __shared__ float p[3];
        __shared__ float h1s[64];
        __shared__ float h2s[128];
        if (t < 3) p[t] = pos[b * 3 + t];
        __syncthreads();
        if (t < 64) {
            float a = b1[t] + p[0] * W1[t] + p[1] * W1[64 + t] + p[2] * W1[128 + t];
            h1s[t] = fmaxf(a, 0.0f);
        }
        __syncthreads();
        if (t < 128) {
            float a = b2[t];
            #pragma unroll 8
            for (int k = 0; k < 64; k++) a += h1s[k] * W2[k * 128 + t];
            h2s[t] = fmaxf(a, 0.0f);
        }
        __syncthreads();
        {
            float a = b3[t];
            #pragma unroll 8
            for (int k = 0; k < 128; k++) a += h2s[k] * W3[k * 256 + t];
            g_feat[b * 256 + t] = a;
        }
    } else if (b == G) {
        // argmin over grid, then scatter-max winner
        __shared__ float ps[G * 3];
        __shared__ float gs[G * 3];
        __shared__ int   idxs[G];
        if (t < G * 3) { ps[t] = pos[t]; gs[t] = gp[t]; }
        __syncthreads();
        if (t < G) {
            const float px = ps[t * 3], py = ps[t * 3 + 1], pz = ps[t * 3 + 2];
            float best = 3.4e38f; int bj = 0;
            #pragma unroll 4
            for (int j = 0; j < G; j++) {
                float dx = px - gs[j * 3];
                float dy = py - gs[j * 3 + 1];
                float dz = pz - gs[j * 3 + 2];
                float d = dx * dx + dy * dy + dz * dz;
                if (d < best) { best = d; bj = j; }   // strict < -> first index on ties (argmin)
            }
            idxs[t] = bj;
        }
        __syncthreads();
        if (t < G) {
            int w = -1;
            for (int i = 0; i < G; i++)
                if (idxs[i] == t) w = i;              // ascending i -> final = max i
            g_winner[t] = w;
        }
    } else if (b < G + 1 + 64) {
        // Transpose Wn1 -> g_Wn1T ; block handles 4 output rows (d)
        const int d0 = (b - (G + 1)) * 4;
        #pragma unroll
        for (int r = 0; r < 4; r++) {
            int d = d0 + r;
            g_Wn1T[d * 256 + t] = Wn1[t * 256 + d];
        }
    } else {
        // Transpose Wn2 -> g_Wn2T
        const int d0 = (b - (G + 1 + 64)) * 4;
        #pragma unroll
        for (int r = 0; r < 4; r++) {
            int d = d0 + r;
            g_Wn2T[d * 256 + t] = Wn2[t * 256 + d];
        }
    }
}

__global__ void k_mid(const float* __restrict__ bn1, const float* __restrict__ bn2)
{
    const int g = blockIdx.x;
    const int t = threadIdx.x;
    __shared__ __align__(16) float gf[256];
    __shared__ __align__(16) float ts[256];

    const int w = g_winner[g];
    gf[t] = (w >= 0) ? g_feat[w * 256 + t] : 0.0f;
    __syncthreads();

    // t_row = relu(gf @ Wn1 + bn1): thread t owns output column t, dot over 256
    {
        const float4* gf4 = (const float4*)gf;
        const float4* w4  = (const float4*)(g_Wn1T + t * 256);
        float a = bn1[t];
        #pragma unroll 8
        for (int c = 0; c < 64; c++) {
            float4 gv = gf4[c];
            float4 wv = w4[c];
            a += gv.x * wv.x + gv.y * wv.y + gv.z * wv.z + gv.w * wv.w;
        }
        ts[t] = fmaxf(a, 0.0f);
    }
    __syncthreads();

    // y_row = t_row @ Wn2 + bn2
    {
        const float4* t4 = (const float4*)ts;
        const float4* w4 = (const float4*)(g_Wn2T + t * 256);
        float a = bn2[t];
        #pragma unroll 8
        for (int c = 0; c < 64; c++) {
            float4 tv = t4[c];
            float4 wv = w4[c];
            a += tv.x * wv.x + tv.y * wv.y + tv.z * wv.z + tv.w * wv.w;
        }
        g_y[g * 256 + t] = a;
    }
}

__global__ void k_head(const float* __restrict__ Wh1, const float* __restrict__ bh1,
                       const float* __restrict__ Wh2, const float* __restrict__ bh2,
                       float* __restrict__ out)
{
    const int t = threadIdx.x;
    __shared__ float agg[256];
    __shared__ __align__(16) float4 part[256];
    __shared__ float h1s[512];

    // agg[c] = mean over 64 grid rows of y[g][c] (deterministic serial sum)
    {
        float s = 0.0f;
        #pragma unroll 8
        for (int g = 0; g < G; g++) s += g_y[g * 256 + t];
        agg[t] = s * (1.0f / 64.0f);
    }
    __syncthreads();

    // heads: h1[k][d] = relu(sum_c agg[c]*Wh1[k][c][d] + bh1[k][d])
    // 512 outputs as 128 float4-groups; c-range split in 2 halves across threads
    {
        const int grp  = t & 127;          // output group (k,d0)
        const int half = t >> 7;           // c-half
        const int k    = grp >> 5;
        const int d0   = (grp & 31) * 4;
        const float* wbase = Wh1 + k * 256 * 128;
        float4 acc = make_float4(0.f, 0.f, 0.f, 0.f);
        const int c0 = half * 128;
        #pragma unroll 8
        for (int c = c0; c < c0 + 128; c++) {
            float av = agg[c];
            float4 wv = *(const float4*)(wbase + c * 128 + d0);
            acc.x += av * wv.x; acc.y += av * wv.y;
            acc.z += av * wv.z; acc.w += av * wv.w;
        }
        part[t] = acc;
    }
    __syncthreads();
    if (t < 128) {
        float4 a0 = part[t];
        float4 a1 = part[t + 128];
        const int k  = t >> 5;
        const int d0 = (t & 31) * 4;
        const int o  = k * 128 + d0;
        h1s[o + 0] = fmaxf(a0.x + a1.x + bh1[o + 0], 0.0f);
        h1s[o + 1] = fmaxf(a0.y + a1.y + bh1[o + 1], 0.0f);
        h1s[o + 2] = fmaxf(a0.z + a1.z + bh1[o + 2], 0.0f);
        h1s[o + 3] = fmaxf(a0.w + a1.w + bh1[o + 3], 0.0f);
    }
    __syncthreads();

    // props[k] = sum_d h1[k][d]*Wh2[k][d] + bh2[k]  (one warp per k)
    const int wid  = t >> 5;
    const int lane = t & 31;
    if (wid < 4) {
        float a = 0.0f;
        #pragma unroll
        for (int j = lane; j < 128; j += 32)
            a += h1s[wid * 128 + j] * Wh2[wid * 128 + j];
        #pragma unroll
        for (int off = 16; off; off >>= 1)
            a += __shfl_xor_sync(0xffffffff, a, off);
        if (lane == 0) out[wid] = a + bh2[wid];
    }
}

extern "C" void kernel_launch(void* const* d_in, const int* in_sizes, int n_in,
                              void* d_out, int out_size)
{
    const float* positions = (const float*)d_in[0];
    const float* grid_pts  = (const float*)d_in[1];
    const float* W1  = (const float*)d_in[2];
    const float* b1  = (const float*)d_in[3];
    const float* W2  = (const float*)d_in[4];
    const float* b2  = (const float*)d_in[5];
    const float* W3  = (const float*)d_in[6];
    const float* b3  = (const float*)d_in[7];
    const float* Wn1 = (const float*)d_in[8];
    const float* bn1 = (const float*)d_in[9];
    const float* Wn2 = (const float*)d_in[10];
    const float* bn2 = (const float*)d_in[11];
    const float* Wh1 = (const float*)d_in[12];
    const float* bh1 = (const float*)d_in[13];
    const float* Wh2 = (const float*)d_in[14];
    const float* bh2 = (const float*)d_in[15];
    float* out = (float*)d_out;

    k_prep<<<G + 1 + 128, 256>>>(positions, grid_pts, W1, b1, W2, b2, W3, b3, Wn1, Wn2);
    k_mid<<<G, 256>>>(bn1, bn2);
    k_head<<<1, 256>>>(Wh1, bh1, Wh2, bh2, out);
}

// round 2
// speedup vs baseline: 1.5702x; 1.5702x over previous
#include <cuda_runtime.h>
#include <cuda_bf16.h>

// ---------------------------------------------------------------------------
// Fully fused persistent kernel. Only feat[0:64] is live (winner in -1..63),
// so the 500K-row MLP collapses to 64 rows. One launch, 112 co-resident
// blocks, 3 internal grid syncs (monotonic-ticket spin; replay-safe):
//   A: rows MLP (blk 0-63) | winner (blk 64) | L2-prefetch Wn1/Wn2/Wh1 (65-111)
//   B: y = relu(gather@Wn1+bn1)@Wn2+bn2      (blk 0-63, coalesced row-major)
//   C: agg = mean_g(y); z = agg@Wh1          (blk 0-63, 8 outputs each)
//   D: out[k] = relu(z+bh1)[k,:] . Wh2[k] + bh2[k]   (blk 0)
// ---------------------------------------------------------------------------

#define G   64
#define NB  112
#define NPREF (NB - (G + 1))   // 47 prefetch blocks

__device__ float g_feat[G * 256];
__device__ int   g_winner[G];
__device__ float g_y[G * 256];
__device__ float g_z[512];
__device__ unsigned long long g_ctr;   // monotonic across launches/replays
__device__ float g_sink;

__device__ __forceinline__ void gsync()
{
    __syncthreads();
    if (threadIdx.x == 0) {
        __threadfence();
        unsigned long long ticket = atomicAdd(&g_ctr, 1ULL) + 1ULL;
        unsigned long long target = ((ticket + (NB - 1)) / NB) * (unsigned long long)NB;
        volatile unsigned long long* p = (volatile unsigned long long*)&g_ctr;
        while (*p < target) { __nanosleep(32); }
        __threadfence();
    }
    __syncthreads();
}

__global__ void __launch_bounds__(256, 1)
fused_kernel(const float* __restrict__ pos, const float* __restrict__ gp,
             const float* __restrict__ W1,  const float* __restrict__ b1,
             const float* __restrict__ W2,  const float* __restrict__ b2,
             const float* __restrict__ W3,  const float* __restrict__ b3,
             const float* __restrict__ Wn1, const float* __restrict__ bn1,
             const float* __restrict__ Wn2, const float* __restrict__ bn2,
             const float* __restrict__ Wh1, const float* __restrict__ bh1,
             const float* __restrict__ Wh2, const float* __restrict__ bh2,
             float* __restrict__ out)
{
    const int b = blockIdx.x;
    const int t = threadIdx.x;

    __shared__ float smA[3 + 64 + 128];        // p / h1 / h2  (phase A mlp)
    __shared__ float smW[G * 3 * 2];           // ps / gs      (phase A winner)
    __shared__ int   smI[G];
    __shared__ float gf[256];                  // phase B in / phase C agg
    __shared__ float ts[256];                  // phase B mid
    __shared__ float h1s[512];                 // phase D

    // ---------------- Phase A ----------------
    if (b < G) {
        float* p   = smA;
        float* h1v = smA + 3;
        float* h2v = smA + 3 + 64;
        if (t < 3) p[t] = pos[b * 3 + t];
        __syncthreads();
        if (t < 64) {
            float a = b1[t] + p[0] * W1[t] + p[1] * W1[64 + t] + p[2] * W1[128 + t];
            h1v[t] = fmaxf(a, 0.0f);
        }
        __syncthreads();
        if (t < 128) {
            float a = b2[t];
            #pragma unroll 16
            for (int k = 0; k < 64; k++) a = fmaf(h1v[k], W2[k * 128 + t], a);
            h2v[t] = fmaxf(a, 0.0f);
        }
        __syncthreads();
        {
            float a = b3[t];
            #pragma unroll 16
            for (int k = 0; k < 128; k++) a = fmaf(h2v[k], W3[k * 256 + t], a);
            g_feat[b * 256 + t] = a;
        }
    } else if (b == G) {
        float* ps = smW;
        float* gs = smW + G * 3;
        if (t < G * 3) { ps[t] = pos[t]; gs[t] = gp[t]; }
        __syncthreads();
        if (t < G) {
            const float px = ps[t * 3], py = ps[t * 3 + 1], pz = ps[t * 3 + 2];
            float best = 3.4e38f; int bj = 0;
            #pragma unroll 4
            for (int j = 0; j < G; j++) {
                float dx = px - gs[j * 3];
                float dy = py - gs[j * 3 + 1];
                float dz = pz - gs[j * 3 + 2];
                float d = dx * dx + dy * dy + dz * dz;
                if (d < best) { best = d; bj = j; }     // argmin: first index on ties
            }
            smI[t] = bj;
        }
        __syncthreads();
        if (t < G) {
            int w = -1;
            for (int i = 0; i < G; i++)
                if (smI[i] == t) w = i;                 // scatter-max (last i wins)
            g_winner[t] = w;
        }
    } else {
        // L2 prefetch of phase B/C/D weights, coalesced float4, overlapped with MLP
        const int  pid    = b - (G + 1);
        const int  stride = NPREF * 256;
        float acc = 0.0f;
        const float4* A1 = (const float4*)Wn1;   // 16384 float4
        const float4* A2 = (const float4*)Wn2;   // 16384
        const float4* A3 = (const float4*)Wh1;   // 32768
        const float4* A4 = (const float4*)Wh2;   // 128
        for (int i = pid * 256 + t; i < 16384; i += stride) { float4 v = A1[i]; acc += v.x + v.y + v.z + v.w; }
        for (int i = pid * 256 + t; i < 16384; i += stride) { float4 v = A2[i]; acc += v.x + v.y + v.z + v.w; }
        for (int i = pid * 256 + t; i < 32768; i += stride) { float4 v = A3[i]; acc += v.x + v.y + v.z + v.w; }
        if (pid == 0 && t < 128) { float4 v = A4[t]; acc += v.x + v.y + v.z + v.w; }
        if (acc == 1.2345678e37f) g_sink = acc;          // never true; keeps loads alive
    }

    gsync();

    // ---------------- Phase B: y = relu(gf@Wn1+bn1)@Wn2+bn2 ----------------
    if (b < G) {
        const int w = g_winner[b];
        gf[t] = (w >= 0) ? g_feat[w * 256 + t] : 0.0f;
        __syncthreads();
        {
            const float* Wp = Wn1 + t;          // coalesced across warp per k
            float a = bn1[t];
            #pragma unroll 16
            for (int k = 0; k < 256; k++) a = fmaf(gf[k], Wp[k * 256], a);
            ts[t] = fmaxf(a, 0.0f);
        }
        __syncthreads();
        {
            const float* Wp = Wn2 + t;
            float a = bn2[t];
            #pragma unroll 16
            for (int k = 0; k < 256; k++) a = fmaf(ts[k], Wp[k * 256], a);
            g_y[b * 256 + t] = a;
        }
    }

    gsync();

    // ---------------- Phase C: agg = mean_g y ; z = agg@Wh1 ----------------
    if (b < G) {
        float s = 0.0f;
        #pragma unroll 16
        for (int g2 = 0; g2 < G; g2++) s += g_y[g2 * 256 + t];
        gf[t] = s * (1.0f / 64.0f);             // reuse gf as agg
        __syncthreads();

        const int lane = t & 31;
        const int wix  = t >> 5;                // 8 warps -> 8 outputs per block
        const int o    = b * 8 + wix;           // 0..511
        const int k    = o >> 7;
        const int d    = o & 127;
        const float* Wb = Wh1 + k * 32768 + d;
        float p = 0.0f;
        #pragma unroll
        for (int j = 0; j < 8; j++) {
            int c = lane + 32 * j;
            p = fmaf(gf[c], Wb[c * 128], p);
        }
        #pragma unroll
        for (int off = 16; off; off >>= 1)
            p += __shfl_xor_sync(0xffffffffu, p, off);
        if (lane == 0) g_z[o] = p;
    }

    gsync();

    // ---------------- Phase D: heads ----------------
    if (b == 0) {
        h1s[t]       = fmaxf(g_z[t]       + bh1[t],       0.0f);
        h1s[t + 256] = fmaxf(g_z[t + 256] + bh1[t + 256], 0.0f);
        __syncthreads();
        const int wid  = t >> 5;
        const int lane = t & 31;
        if (wid < 4) {
            float a = 0.0f;
            #pragma unroll
            for (int j = lane; j < 128; j += 32)
                a += h1s[wid * 128 + j] * Wh2[wid * 128 + j];
            #pragma unroll
            for (int off = 16; off; off >>= 1)
                a += __shfl_xor_sync(0xffffffffu, a, off);
            if (lane == 0) out[wid] = a + bh2[wid];
        }
    }
}

extern "C" void kernel_launch(void* const* d_in, const int* in_sizes, int n_in,
                              void* d_out, int out_size)
{
    const float* positions = (const float*)d_in[0];
    const float* grid_pts  = (const float*)d_in[1];
    const float* W1  = (const float*)d_in[2];
    const float* b1  = (const float*)d_in[3];
    const float* W2  = (const float*)d_in[4];
    const float* b2  = (const float*)d_in[5];
    const float* W3  = (const float*)d_in[6];
    const float* b3  = (const float*)d_in[7];
    const float* Wn1 = (const float*)d_in[8];
    const float* bn1 = (const float*)d_in[9];
    const float* Wn2 = (const float*)d_in[10];
    const float* bn2 = (const float*)d_in[11];
    const float* Wh1 = (const float*)d_in[12];
    const float* bh1 = (const float*)d_in[13];
    const float* Wh2 = (const float*)d_in[14];
    const float* bh2 = (const float*)d_in[15];
    float* out = (float*)d_out;

    fused_kernel<<<NB, 256>>>(positions, grid_pts, W1, b1, W2, b2, W3, b3,
                              Wn1, bn1, Wn2, bn2, Wh1, bh1, Wh2, bh2, out);
}

// round 3
// speedup vs baseline: 2.0829x; 1.3266x over previous
#include <cuda_runtime.h>
#include <cuda_bf16.h>

// ---------------------------------------------------------------------------
// Fused persistent kernel, 65 blocks, 3 internal grid syncs.
// Only feat[0:64] is live (winner in -1..63) -> 500K-row MLP collapses to 64.
//   A: rows MLP (blk 0-63, float4 weight loads) | winner (blk 64)
//   B: y = relu(gather@Wn1+bn1)@Wn2+bn2   (blk 0-31, 2 rows each, float4)
//   C: agg = mean_g(y); z = agg@Wh1       (blk 0-63, 8 outputs each)
//   D: out[k] = relu(z+bh1)[k,:] . Wh2[k] + bh2[k]   (blk 0)
// ---------------------------------------------------------------------------

#define G   64
#define NB  65

__device__ float g_feat[G * 256];
__device__ int   g_winner[G];
__device__ float g_y[G * 256];
__device__ float g_z[512];
__device__ unsigned long long g_ctr;   // monotonic across launches/replays

__device__ __forceinline__ void gsync()
{
    __syncthreads();
    if (threadIdx.x == 0) {
        __threadfence();
        unsigned long long ticket = atomicAdd(&g_ctr, 1ULL) + 1ULL;
        unsigned long long target = ((ticket + (NB - 1)) / NB) * (unsigned long long)NB;
        volatile unsigned long long* p = (volatile unsigned long long*)&g_ctr;
        while (*p < target) { }
        __threadfence();
    }
    __syncthreads();
}

__global__ void __launch_bounds__(256, 1)
fused_kernel(const float* __restrict__ pos, const float* __restrict__ gp,
             const float* __restrict__ W1,  const float* __restrict__ b1,
             const float* __restrict__ W2,  const float* __restrict__ b2,
             const float* __restrict__ W3,  const float* __restrict__ b3,
             const float* __restrict__ Wn1, const float* __restrict__ bn1,
             const float* __restrict__ Wn2, const float* __restrict__ bn2,
             const float* __restrict__ Wh1, const float* __restrict__ bh1,
             const float* __restrict__ Wh2, const float* __restrict__ bh2,
             float* __restrict__ out)
{
    const int b = blockIdx.x;
    const int t = threadIdx.x;

    __shared__ float4 sp4[512];     // chunked partials (8KB), reused per phase
    __shared__ float  sf[1024];     // misc scratch (4KB), reused per phase
    __shared__ int    si[G];

    // ================= Phase A =================
    if (b < G) {
        // per-row MLP 3 -> 64 -> 128 -> 256 for position row b
        float* p  = sf;          // [3]
        float* h1 = sf + 4;      // [64]
        float* h2 = sf + 72;     // [128]
        float* pf = (float*)sp4;
        if (t < 3) p[t] = pos[b * 3 + t];
        __syncthreads();
        if (t < 64) {
            float a = b1[t] + p[0] * W1[t] + p[1] * W1[64 + t] + p[2] * W1[128 + t];
            h1[t] = fmaxf(a, 0.0f);
        }
        __syncthreads();
        // layer2: 128 outs (32 float4 groups), 64 k, 8 chunks x 8 k
        {
            const float4* W = (const float4*)W2;    // [64][32]
            const int c  = t & 31;
            const int ch = t >> 5;
            float4 a = make_float4(0.f, 0.f, 0.f, 0.f);
            #pragma unroll
            for (int j = 0; j < 8; j++) {
                int k = ch * 8 + j;
                float4 w = W[k * 32 + c];
                float  h = h1[k];
                a.x = fmaf(h, w.x, a.x); a.y = fmaf(h, w.y, a.y);
                a.z = fmaf(h, w.z, a.z); a.w = fmaf(h, w.w, a.w);
            }
            sp4[ch * 32 + c] = a;
        }
        __syncthreads();
        if (t < 128) {
            float a = b2[t];
            #pragma unroll
            for (int ch = 0; ch < 8; ch++) a += pf[ch * 128 + t];
            // can't write into h2 yet (pf region distinct from sf) -> safe
            h2[t] = fmaxf(a, 0.0f);
        }
        __syncthreads();
        // layer3: 256 outs (64 groups), 128 k, 4 chunks x 32 k
        {
            const float4* W = (const float4*)W3;    // [128][64]
            const int c  = t & 63;
            const int ch = t >> 6;
            float4 a = make_float4(0.f, 0.f, 0.f, 0.f);
            #pragma unroll 8
            for (int j = 0; j < 32; j++) {
                int k = ch * 32 + j;
                float4 w = W[k * 64 + c];
                float  h = h2[k];
                a.x = fmaf(h, w.x, a.x); a.y = fmaf(h, w.y, a.y);
                a.z = fmaf(h, w.z, a.z); a.w = fmaf(h, w.w, a.w);
            }
            sp4[ch * 64 + c] = a;
        }
        __syncthreads();
        {
            float a = b3[t] + pf[t] + pf[256 + t] + pf[512 + t] + pf[768 + t];
            g_feat[b * 256 + t] = a;
        }
    } else {
        // winner block
        float* ps = sf;          // [192]
        float* gs = sf + 192;    // [192]
        if (t < G * 3) { ps[t] = pos[t]; gs[t] = gp[t]; }
        __syncthreads();
        if (t < G) {
            const float px = ps[t * 3], py = ps[t * 3 + 1], pz = ps[t * 3 + 2];
            float best = 3.4e38f; int bj = 0;
            #pragma unroll 4
            for (int j = 0; j < G; j++) {
                float dx = px - gs[j * 3];
                float dy = py - gs[j * 3 + 1];
                float dz = pz - gs[j * 3 + 2];
                float d = dx * dx + dy * dy + dz * dz;
                if (d < best) { best = d; bj = j; }    // argmin: first idx on ties
            }
            si[t] = bj;
        }
        __syncthreads();
        if (t < G) {
            int w = -1;
            for (int i = 0; i < G; i++)
                if (si[i] == t) w = i;                 // last i == max i
            g_winner[t] = w;
        }
    }

    gsync();

    // ================= Phase B: 32 blocks, 2 rows each =================
    if (b < 32) {
        const int r0 = 2 * b, r1 = r0 + 1;
        float* gf0 = sf;         // [256]
        float* gf1 = sf + 256;
        float* ts0 = sf + 512;
        float* ts1 = sf + 768;
        float* pfl = (float*)sp4;

        const int w0 = g_winner[r0], w1 = g_winner[r1];
        gf0[t] = (w0 >= 0) ? g_feat[w0 * 256 + t] : 0.0f;
        gf1[t] = (w1 >= 0) ? g_feat[w1 * 256 + t] : 0.0f;
        __syncthreads();

        const int c  = t & 63;        // float4 column group (256 cols)
        const int ch = t >> 6;        // 4 chunks x 64 k

        // ---- layer 1: T = relu(GF @ Wn1 + bn1) ----
        {
            const float4* W = (const float4*)Wn1;   // [256][64]
            float4 a0 = make_float4(0.f, 0.f, 0.f, 0.f);
            float4 a1 = make_float4(0.f, 0.f, 0.f, 0.f);
            #pragma unroll 8
            for (int j = 0; j < 64; j++) {
                int k = ch * 64 + j;
                float4 w = W[k * 64 + c];
                float  x0 = gf0[k], x1 = gf1[k];
                a0.x = fmaf(x0, w.x, a0.x); a0.y = fmaf(x0, w.y, a0.y);
                a0.z = fmaf(x0, w.z, a0.z); a0.w = fmaf(x0, w.w, a0.w);
                a1.x = fmaf(x1, w.x, a1.x); a1.y = fmaf(x1, w.y, a1.y);
                a1.z = fmaf(x1, w.z, a1.z); a1.w = fmaf(x1, w.w, a1.w);
            }
            sp4[ch * 64 + c]       = a0;
            sp4[256 + ch * 64 + c] = a1;
        }
        __syncthreads();
        {
            float bn = bn1[t];
            float v0 = bn + pfl[t] + pfl[256 + t] + pfl[512 + t] + pfl[768 + t];
            float v1 = bn + pfl[1024 + t] + pfl[1280 + t] + pfl[1536 + t] + pfl[1792 + t];
            ts0[t] = fmaxf(v0, 0.0f);
            ts1[t] = fmaxf(v1, 0.0f);
        }
        __syncthreads();

        // ---- layer 2: Y = T @ Wn2 + bn2 ----
        {
            const float4* W = (const float4*)Wn2;
            float4 a0 = make_float4(0.f, 0.f, 0.f, 0.f);
            float4 a1 = make_float4(0.f, 0.f, 0.f, 0.f);
            #pragma unroll 8
            for (int j = 0; j < 64; j++) {
                int k = ch * 64 + j;
                float4 w = W[k * 64 + c];
                float  x0 = ts0[k], x1 = ts1[k];
                a0.x = fmaf(x0, w.x, a0.x); a0.y = fmaf(x0, w.y, a0.y);
                a0.z = fmaf(x0, w.z, a0.z); a0.w = fmaf(x0, w.w, a0.w);
                a1.x = fmaf(x1, w.x, a1.x); a1.y = fmaf(x1, w.y, a1.y);
                a1.z = fmaf(x1, w.z, a1.z); a1.w = fmaf(x1, w.w, a1.w);
            }
            sp4[ch * 64 + c]       = a0;
            sp4[256 + ch * 64 + c] = a1;
        }
        __syncthreads();
        {
            float bn = bn2[t];
            float v0 = bn + pfl[t] + pfl[256 + t] + pfl[512 + t] + pfl[768 + t];
            float v1 = bn + pfl[1024 + t] + pfl[1280 + t] + pfl[1536 + t] + pfl[1792 + t];
            g_y[r0 * 256 + t] = v0;
            g_y[r1 * 256 + t] = v1;
        }
    }

    gsync();

    // ================= Phase C: agg + z =================
    if (b < G) {
        float* agg = sf;         // [256]
        float* pfl = (float*)sp4;
        // agg = mean over 64 rows of g_y (float4 loads, 4 row-chunks x 16)
        {
            const float4* Y = (const float4*)g_y;   // [64][64]
            const int c  = t & 63;
            const int rc = t >> 6;
            float4 a = make_float4(0.f, 0.f, 0.f, 0.f);
            #pragma unroll
            for (int j = 0; j < 16; j++) {
                int r = rc * 16 + j;
                float4 v = Y[r * 64 + c];
                a.x += v.x; a.y += v.y; a.z += v.z; a.w += v.w;
            }
            sp4[rc * 64 + c] = a;
        }
        __syncthreads();
        agg[t] = (pfl[t] + pfl[256 + t] + pfl[512 + t] + pfl[768 + t]) * (1.0f / 64.0f);
        __syncthreads();

        // z: 8 outputs per block, one warp each
        const int lane = t & 31;
        const int wix  = t >> 5;
        const int o    = b * 8 + wix;          // 0..511
        const int k    = o >> 7;
        const int d    = o & 127;
        const float* Wb = Wh1 + k * 32768 + d;
        float pz = 0.0f;
        #pragma unroll
        for (int j = 0; j < 8; j++) {
            int cc = lane + 32 * j;
            pz = fmaf(agg[cc], Wb[cc * 128], pz);
        }
        #pragma unroll
        for (int off = 16; off; off >>= 1)
            pz += __shfl_xor_sync(0xffffffffu, pz, off);
        if (lane == 0) g_z[o] = pz;
    }

    gsync();

    // ================= Phase D: heads (block 0) =================
    if (b == 0) {
        float* h1s = sf + 256;   // [512]
        h1s[t]       = fmaxf(g_z[t]       + bh1[t],       0.0f);
        h1s[t + 256] = fmaxf(g_z[t + 256] + bh1[t + 256], 0.0f);
        __syncthreads();
        const int wid  = t >> 5;
        const int lane = t & 31;
        if (wid < 4) {
            float a = 0.0f;
            #pragma unroll
            for (int j = lane; j < 128; j += 32)
                a += h1s[wid * 128 + j] * Wh2[wid * 128 + j];
            #pragma unroll
            for (int off = 16; off; off >>= 1)
                a += __shfl_xor_sync(0xffffffffu, a, off);
            if (lane == 0) out[wid] = a + bh2[wid];
        }
    }
}

extern "C" void kernel_launch(void* const* d_in, const int* in_sizes, int n_in,
                              void* d_out, int out_size)
{
    const float* positions = (const float*)d_in[0];
    const float* grid_pts  = (const float*)d_in[1];
    const float* W1  = (const float*)d_in[2];
    const float* b1  = (const float*)d_in[3];
    const float* W2  = (const float*)d_in[4];
    const float* b2  = (const float*)d_in[5];
    const float* W3  = (const float*)d_in[6];
    const float* b3  = (const float*)d_in[7];
    const float* Wn1 = (const float*)d_in[8];
    const float* bn1 = (const float*)d_in[9];
    const float* Wn2 = (const float*)d_in[10];
    const float* bn2 = (const float*)d_in[11];
    const float* Wh1 = (const float*)d_in[12];
    const float* bh1 = (const float*)d_in[13];
    const float* Wh2 = (const float*)d_in[14];
    const float* bh2 = (const float*)d_in[15];
    float* out = (float*)d_out;

    fused_kernel<<<NB, 256>>>(positions, grid_pts, W1, b1, W2, b2, W3, b3,
                              Wn1, bn1, Wn2, bn2, Wh1, bh1, Wh2, bh2, out);
}

// round 4
// speedup vs baseline: 2.2924x; 1.1006x over previous
#include <cuda_runtime.h>
#include <cuda_bf16.h>

// ---------------------------------------------------------------------------
// Two-phase fused persistent kernel, 64 blocks, ONE internal grid sync.
// Only feat[0:64] is live (winner in -1..63) -> 500K-row MLP collapses to 64.
//
// Phase AB (blocks 0-63, block b owns grid row b):
//   - redundantly compute full argmin table idx[0:64] (pos vs grid_points)
//   - winner_b = max{i : idx[i]==b} (scatter-max), -1 if none
//   - gf = MLP(pos[winner_b]) (3->64->128->256), or 0 if winner_b<0
//   - y_b = relu(gf@Wn1+bn1)@Wn2+bn2 -> g_y[b]
// gsync
// Phase CD (blocks 0-3, block k owns head k):
//   - agg = mean_g(g_y)  (redundant per block)
//   - z = agg@Wh1[k]; h1 = relu(z+bh1[k]); out[k] = h1.Wh2[k]+bh2[k]
// ---------------------------------------------------------------------------

#define G   64
#define NB  64

__device__ float g_y[G * 256];
__device__ unsigned long long g_ctr;   // monotonic across launches/replays

__device__ __forceinline__ void gsync()
{
    __syncthreads();
    if (threadIdx.x == 0) {
        __threadfence();
        unsigned long long ticket = atomicAdd(&g_ctr, 1ULL) + 1ULL;
        unsigned long long target = ((ticket + (NB - 1)) / NB) * (unsigned long long)NB;
        volatile unsigned long long* p = (volatile unsigned long long*)&g_ctr;
        while (*p < target) { }
        __threadfence();
    }
    __syncthreads();
}

__global__ void __launch_bounds__(256, 1)
fused_kernel(const float* __restrict__ pos, const float* __restrict__ gp,
             const float* __restrict__ W1,  const float* __restrict__ b1,
             const float* __restrict__ W2,  const float* __restrict__ b2,
             const float* __restrict__ W3,  const float* __restrict__ b3,
             const float* __restrict__ Wn1, const float* __restrict__ bn1,
             const float* __restrict__ Wn2, const float* __restrict__ bn2,
             const float* __restrict__ Wh1, const float* __restrict__ bh1,
             const float* __restrict__ Wh2, const float* __restrict__ bh2,
             float* __restrict__ out)
{
    const int b = blockIdx.x;
    const int t = threadIdx.x;

    __shared__ float4 sp4[512];         // partials scratch (8 KB)
    __shared__ float  sf[1024];         // general scratch  (4 KB)
    __shared__ int    si[G];
    __shared__ int    s_w[2];

    // ================= Phase AB =================
    {
        // ---- winner table (redundant in every block) ----
        float* ps = sf;                 // [192]
        float* gs = sf + 192;           // [192]
        if (t < G * 3) { ps[t] = pos[t]; gs[t] = gp[t]; }
        __syncthreads();
        if (t < G) {
            const float px = ps[t * 3], py = ps[t * 3 + 1], pz = ps[t * 3 + 2];
            float best = 3.4e38f; int bj = 0;
            #pragma unroll 4
            for (int j = 0; j < G; j++) {
                float dx = px - gs[j * 3];
                float dy = py - gs[j * 3 + 1];
                float dz = pz - gs[j * 3 + 2];
                float d  = dx * dx + dy * dy + dz * dz;
                if (d < best) { best = d; bj = j; }   // argmin: first idx on ties
            }
            si[t] = bj;
        }
        __syncthreads();
        // winner_b = max i with si[i]==b  (2 warps of candidates -> smem max)
        if (t < G) {
            int cand = (si[t] == b) ? t : -1;
            #pragma unroll
            for (int off = 16; off; off >>= 1)
                cand = max(cand, __shfl_xor_sync(0xffffffffu, cand, off));
            if ((t & 31) == 0) s_w[t >> 5] = cand;
        }
        __syncthreads();
        const int w = max(s_w[0], s_w[1]);

        // ---- gf = MLP(pos[w]) or 0 ----
        float* gf = sf + 384;           // [256]
        float* pf = (float*)sp4;

        if (w >= 0) {
            float* p  = sf;             // reuse: [3]  (ps no longer needed)
            float* h1 = sf + 8;         // [64]
            float* h2 = sf + 80;        // [128]
            __syncthreads();            // protect ps before overwrite
            if (t < 3) p[t] = pos[w * 3 + t];
            __syncthreads();
            if (t < 64) {
                float a = b1[t] + p[0] * W1[t] + p[1] * W1[64 + t] + p[2] * W1[128 + t];
                h1[t] = fmaxf(a, 0.0f);
            }
            __syncthreads();
            // layer2: 128 outs = 32 float4 groups, 8 chunks x 8 k
            {
                const float4* W = (const float4*)W2;     // [64][32]
                const int c  = t & 31;
                const int ch = t >> 5;
                float4 a = make_float4(0.f, 0.f, 0.f, 0.f);
                #pragma unroll
                for (int j = 0; j < 8; j++) {
                    int k = ch * 8 + j;
                    float4 wv = W[k * 32 + c];
                    float  h  = h1[k];
                    a.x = fmaf(h, wv.x, a.x); a.y = fmaf(h, wv.y, a.y);
                    a.z = fmaf(h, wv.z, a.z); a.w = fmaf(h, wv.w, a.w);
                }
                sp4[ch * 32 + c] = a;
            }
            __syncthreads();
            if (t < 128) {
                float a = b2[t];
                #pragma unroll
                for (int ch = 0; ch < 8; ch++) a += pf[ch * 128 + t];
                h2[t] = fmaxf(a, 0.0f);
            }
            __syncthreads();
            // layer3: 256 outs = 64 groups, 4 chunks x 32 k
            {
                const float4* W = (const float4*)W3;     // [128][64]
                const int c  = t & 63;
                const int ch = t >> 6;
                float4 a = make_float4(0.f, 0.f, 0.f, 0.f);
                #pragma unroll 8
                for (int j = 0; j < 32; j++) {
                    int k = ch * 32 + j;
                    float4 wv = W[k * 64 + c];
                    float  h  = h2[k];
                    a.x = fmaf(h, wv.x, a.x); a.y = fmaf(h, wv.y, a.y);
                    a.z = fmaf(h, wv.z, a.z); a.w = fmaf(h, wv.w, a.w);
                }
                sp4[ch * 64 + c] = a;
            }
            __syncthreads();
            gf[t] = b3[t] + pf[t] + pf[256 + t] + pf[512 + t] + pf[768 + t];
        } else {
            __syncthreads();
            gf[t] = 0.0f;
        }
        __syncthreads();

        // ---- y_b = relu(gf@Wn1+bn1)@Wn2+bn2 ----
        float* ts = sf;                 // [256] (ps/gs/p/h dead now)
        const int c  = t & 63;          // float4 col group (256 cols)
        const int ch = t >> 6;          // 4 chunks x 64 k
        {
            const float4* W = (const float4*)Wn1;        // [256][64]
            float4 a = make_float4(0.f, 0.f, 0.f, 0.f);
            #pragma unroll 8
            for (int j = 0; j < 64; j++) {
                int k = ch * 64 + j;
                float4 wv = W[k * 64 + c];
                float  x  = gf[k];
                a.x = fmaf(x, wv.x, a.x); a.y = fmaf(x, wv.y, a.y);
                a.z = fmaf(x, wv.z, a.z); a.w = fmaf(x, wv.w, a.w);
            }
            sp4[ch * 64 + c] = a;
        }
        __syncthreads();
        ts[t] = fmaxf(bn1[t] + pf[t] + pf[256 + t] + pf[512 + t] + pf[768 + t], 0.0f);
        __syncthreads();
        {
            const float4* W = (const float4*)Wn2;
            float4 a = make_float4(0.f, 0.f, 0.f, 0.f);
            #pragma unroll 8
            for (int j = 0; j < 64; j++) {
                int k = ch * 64 + j;
                float4 wv = W[k * 64 + c];
                float  x  = ts[k];
                a.x = fmaf(x, wv.x, a.x); a.y = fmaf(x, wv.y, a.y);
                a.z = fmaf(x, wv.z, a.z); a.w = fmaf(x, wv.w, a.w);
            }
            sp4[ch * 64 + c] = a;
        }
        __syncthreads();
        g_y[b * 256 + t] = bn2[t] + pf[t] + pf[256 + t] + pf[512 + t] + pf[768 + t];
    }

    gsync();

    // ================= Phase CD: blocks 0-3, head k = b =================
    if (b < 4) {
        const int k = b;
        float* agg = sf;                // [256]
        float* pfl = (float*)sp4;
        // agg = mean over 64 rows of g_y (float4, 4 row-chunks x 16)
        {
            const float4* Y = (const float4*)g_y;        // [64][64]
            const int c  = t & 63;
            const int rc = t >> 6;
            float4 a = make_float4(0.f, 0.f, 0.f, 0.f);
            #pragma unroll
            for (int j = 0; j < 16; j++) {
                float4 v = Y[(rc * 16 + j) * 64 + c];
                a.x += v.x; a.y += v.y; a.z += v.z; a.w += v.w;
            }
            sp4[rc * 64 + c] = a;
        }
        __syncthreads();
        agg[t] = (pfl[t] + pfl[256 + t] + pfl[512 + t] + pfl[768 + t]) * (1.0f / 64.0f);
        __syncthreads();

        // z = agg @ Wh1[k]: 32 float4 d-groups x 8 c-slices
        {
            const int dg   = t & 31;    // d0 = dg*4
            const int half = t >> 5;    // c-slice (8 x 32)
            const float* Wb = Wh1 + k * 32768 + dg * 4;
            float4 acc = make_float4(0.f, 0.f, 0.f, 0.f);
            const int c0 = half * 32;
            #pragma unroll 8
            for (int c2 = c0; c2 < c0 + 32; c2++) {
                float  av = agg[c2];
                float4 wv = *(const float4*)(Wb + c2 * 128);
                acc.x = fmaf(av, wv.x, acc.x); acc.y = fmaf(av, wv.y, acc.y);
                acc.z = fmaf(av, wv.z, acc.z); acc.w = fmaf(av, wv.w, acc.w);
            }
            sp4[t] = acc;
        }
        __syncthreads();
        float* h1s = sf + 256;          // [128]
        if (t < 32) {
            float4 a = sp4[t];
            #pragma unroll
            for (int s = 1; s < 8; s++) {
                float4 v = sp4[t + 32 * s];
                a.x += v.x; a.y += v.y; a.z += v.z; a.w += v.w;
            }
            const int o = t * 4;
            h1s[o + 0] = fmaxf(a.x + bh1[k * 128 + o + 0], 0.0f);
            h1s[o + 1] = fmaxf(a.y + bh1[k * 128 + o + 1], 0.0f);
            h1s[o + 2] = fmaxf(a.z + bh1[k * 128 + o + 2], 0.0f);
            h1s[o + 3] = fmaxf(a.w + bh1[k * 128 + o + 3], 0.0f);
        }
        __syncthreads();
        if (t < 32) {
            float a = 0.0f;
            #pragma unroll
            for (int j = t; j < 128; j += 32)
                a = fmaf(h1s[j], Wh2[k * 128 + j], a);
            #pragma unroll
            for (int off = 16; off; off >>= 1)
                a += __shfl_xor_sync(0xffffffffu, a, off);
            if (t == 0) out[k] = a + bh2[k];
        }
    }
}

extern "C" void kernel_launch(void* const* d_in, const int* in_sizes, int n_in,
                              void* d_out, int out_size)
{
    const float* positions = (const float*)d_in[0];
    const float* grid_pts  = (const float*)d_in[1];
    const float* W1  = (const float*)d_in[2];
    const float* b1  = (const float*)d_in[3];
    const float* W2  = (const float*)d_in[4];
    const float* b2  = (const float*)d_in[5];
    const float* W3  = (const float*)d_in[6];
    const float* b3  = (const float*)d_in[7];
    const float* Wn1 = (const float*)d_in[8];
    const float* bn1 = (const float*)d_in[9];
    const float* Wn2 = (const float*)d_in[10];
    const float* bn2 = (const float*)d_in[11];
    const float* Wh1 = (const float*)d_in[12];
    const float* bh1 = (const float*)d_in[13];
    const float* Wh2 = (const float*)d_in[14];
    const float* bh2 = (const float*)d_in[15];
    float* out = (float*)d_out;

    fused_kernel<<<NB, 256>>>(positions, grid_pts, W1, b1, W2, b2, W3, b3,
                              Wn1, bn1, Wn2, bn2, Wh1, bh1, Wh2, bh2, out);
}

// round 5
// speedup vs baseline: 2.6530x; 1.1573x over previous
#include <cuda_runtime.h>
#include <cuda_bf16.h>
#include <cooperative_groups.h>

namespace cg = cooperative_groups;

// ---------------------------------------------------------------------------
// Fused persistent kernel, 128 blocks = 64 clusters of 2, ONE grid sync.
// Only feat[0:64] is live (winner in -1..63) -> 500K-row MLP collapses to 64.
//
// Cluster (row r = blockIdx.x/2, half h = rank):
//   - winner table redundant; w = winner_r
//   - gf = MLP(pos[w]) (redundant in both halves; W2+W3 = 160KB)
//   - ts half: relu(gf @ Wn1[:, h*128:+128] + bn1)   (reads half of Wn1)
//   - cluster.sync; fetch peer ts half via DSMEM -> full ts
//   - y half: ts @ Wn2[:, h*128:+128] + bn2 -> g_y[r, half]
// gsync (128 blocks)
//   - blocks 0-3: agg = mean(g_y); head k=b -> out[k]
// ---------------------------------------------------------------------------

#define G   64
#define NB  128

__device__ float g_y[G * 256];
__device__ unsigned long long g_ctr;   // monotonic across launches/replays

__device__ __forceinline__ void gsync()
{
    __syncthreads();
    if (threadIdx.x == 0) {
        __threadfence();
        unsigned long long ticket = atomicAdd(&g_ctr, 1ULL) + 1ULL;
        unsigned long long target = ((ticket + (NB - 1)) / NB) * (unsigned long long)NB;
        volatile unsigned long long* p = (volatile unsigned long long*)&g_ctr;
        while (*p < target) { }
        __threadfence();
    }
    __syncthreads();
}

struct SmemLayout {
    float  ts[256];        // full ts row (own half written, peer half copied)
    float4 sp4[256];       // chunk partials
    float  ps[192];
    float  gs[192];
    float  gf[256];
    float  h1[64];
    float  h2[128];
    float  p[4];
    float  h1s[128];
    int    si[G];
    int    s_w[2];
};

__global__ void __launch_bounds__(256, 1) __cluster_dims__(2, 1, 1)
fused_kernel(const float* __restrict__ pos, const float* __restrict__ gp,
             const float* __restrict__ W1,  const float* __restrict__ b1,
             const float* __restrict__ W2,  const float* __restrict__ b2,
             const float* __restrict__ W3,  const float* __restrict__ b3,
             const float* __restrict__ Wn1, const float* __restrict__ bn1,
             const float* __restrict__ Wn2, const float* __restrict__ bn2,
             const float* __restrict__ Wh1, const float* __restrict__ bh1,
             const float* __restrict__ Wh2, const float* __restrict__ bh2,
             float* __restrict__ out)
{
    __shared__ SmemLayout sm;
    const int b = blockIdx.x;
    const int t = threadIdx.x;
    const int r = b >> 1;              // grid row owned by this cluster
    cg::cluster_group cluster = cg::this_cluster();
    const unsigned h = cluster.block_rank();   // 0 or 1: column half

    // ---- winner table (redundant) ----
    if (t < G * 3) { sm.ps[t] = pos[t]; sm.gs[t] = gp[t]; }
    __syncthreads();
    if (t < G) {
        const float px = sm.ps[t * 3], py = sm.ps[t * 3 + 1], pz = sm.ps[t * 3 + 2];
        float best = 3.4e38f; int bj = 0;
        #pragma unroll 4
        for (int j = 0; j < G; j++) {
            float dx = px - sm.gs[j * 3];
            float dy = py - sm.gs[j * 3 + 1];
            float dz = pz - sm.gs[j * 3 + 2];
            float d  = dx * dx + dy * dy + dz * dz;
            if (d < best) { best = d; bj = j; }     // argmin: first idx on ties
        }
        sm.si[t] = bj;
    }
    __syncthreads();
    if (t < G) {
        int cand = (sm.si[t] == r) ? t : -1;
        #pragma unroll
        for (int off = 16; off; off >>= 1)
            cand = max(cand, __shfl_xor_sync(0xffffffffu, cand, off));
        if ((t & 31) == 0) sm.s_w[t >> 5] = cand;
    }
    __syncthreads();
    const int w = max(sm.s_w[0], sm.s_w[1]);

    // ---- gf = MLP(pos[w]) or 0 (redundant in both halves) ----
    float* pf = (float*)sm.sp4;
    if (w >= 0) {
        if (t < 3) sm.p[t] = pos[w * 3 + t];
        __syncthreads();
        if (t < 64) {
            float a = b1[t] + sm.p[0] * W1[t] + sm.p[1] * W1[64 + t] + sm.p[2] * W1[128 + t];
            sm.h1[t] = fmaxf(a, 0.0f);
        }
        __syncthreads();
        {   // layer2: 128 outs = 32 float4 groups, 8 chunks x 8 k
            const float4* W = (const float4*)W2;    // [64][32]
            const int c  = t & 31;
            const int ch = t >> 5;
            float4 a = make_float4(0.f, 0.f, 0.f, 0.f);
            #pragma unroll
            for (int j = 0; j < 8; j++) {
                int k = ch * 8 + j;
                float4 wv = W[k * 32 + c];
                float  x  = sm.h1[k];
                a.x = fmaf(x, wv.x, a.x); a.y = fmaf(x, wv.y, a.y);
                a.z = fmaf(x, wv.z, a.z); a.w = fmaf(x, wv.w, a.w);
            }
            sm.sp4[ch * 32 + c] = a;
        }
        __syncthreads();
        if (t < 128) {
            float a = b2[t];
            #pragma unroll
            for (int ch = 0; ch < 8; ch++) a += pf[ch * 128 + t];
            sm.h2[t] = fmaxf(a, 0.0f);
        }
        __syncthreads();
        {   // layer3: 256 outs = 64 groups, 4 chunks x 32 k
            const float4* W = (const float4*)W3;    // [128][64]
            const int c  = t & 63;
            const int ch = t >> 6;
            float4 a = make_float4(0.f, 0.f, 0.f, 0.f);
            #pragma unroll
            for (int j = 0; j < 32; j++) {
                int k = ch * 32 + j;
                float4 wv = W[k * 64 + c];
                float  x  = sm.h2[k];
                a.x = fmaf(x, wv.x, a.x); a.y = fmaf(x, wv.y, a.y);
                a.z = fmaf(x, wv.z, a.z); a.w = fmaf(x, wv.w, a.w);
            }
            sm.sp4[ch * 64 + c] = a;
        }
        __syncthreads();
        sm.gf[t] = b3[t] + pf[t] + pf[256 + t] + pf[512 + t] + pf[768 + t];
    } else {
        sm.gf[t] = 0.0f;
    }
    __syncthreads();

    // ---- ts half: cols [h*128, h*128+128) ; 8 chunks x 32 k, 32 col-groups ----
    {
        const float4* W = (const float4*)Wn1;       // [256][64]
        const int c  = t & 31;                      // col group within half
        const int ch = t >> 5;                      // 8 chunks x 32 k
        const int cg4 = h * 32 + c;                 // absolute float4 col group
        float4 a = make_float4(0.f, 0.f, 0.f, 0.f);
        #pragma unroll
        for (int j = 0; j < 32; j++) {
            int k = ch * 32 + j;
            float4 wv = W[k * 64 + cg4];
            float  x  = sm.gf[k];
            a.x = fmaf(x, wv.x, a.x); a.y = fmaf(x, wv.y, a.y);
            a.z = fmaf(x, wv.z, a.z); a.w = fmaf(x, wv.w, a.w);
        }
        sm.sp4[ch * 32 + c] = a;
    }
    __syncthreads();
    if (t < 32) {
        float4 a = sm.sp4[t];
        #pragma unroll
        for (int s = 1; s < 8; s++) {
            float4 v = sm.sp4[t + 32 * s];
            a.x += v.x; a.y += v.y; a.z += v.z; a.w += v.w;
        }
        const int o = h * 128 + t * 4;              // absolute column
        sm.ts[o + 0] = fmaxf(a.x + bn1[o + 0], 0.0f);
        sm.ts[o + 1] = fmaxf(a.y + bn1[o + 1], 0.0f);
        sm.ts[o + 2] = fmaxf(a.z + bn1[o + 2], 0.0f);
        sm.ts[o + 3] = fmaxf(a.w + bn1[o + 3], 0.0f);
    }

    // ---- exchange ts halves via DSMEM ----
    cluster.sync();
    {
        const unsigned peer = h ^ 1u;
        const float* peer_ts = cluster.map_shared_rank((const float*)sm.ts, peer);
        if (t < 32) {
            const int o = peer * 128 + t * 4;       // peer's half
            float4 v = *(const float4*)(peer_ts + o);
            *(float4*)(sm.ts + o) = v;
        }
    }
    __syncthreads();

    // ---- y half: ts @ Wn2[:, half] + bn2 -> g_y ----
    {
        const float4* W = (const float4*)Wn2;
        const int c  = t & 31;
        const int ch = t >> 5;
        const int cg4 = h * 32 + c;
        float4 a = make_float4(0.f, 0.f, 0.f, 0.f);
        #pragma unroll
        for (int j = 0; j < 32; j++) {
            int k = ch * 32 + j;
            float4 wv = W[k * 64 + cg4];
            float  x  = sm.ts[k];
            a.x = fmaf(x, wv.x, a.x); a.y = fmaf(x, wv.y, a.y);
            a.z = fmaf(x, wv.z, a.z); a.w = fmaf(x, wv.w, a.w);
        }
        sm.sp4[ch * 32 + c] = a;
    }
    __syncthreads();
    if (t < 32) {
        float4 a = sm.sp4[t];
        #pragma unroll
        for (int s = 1; s < 8; s++) {
            float4 v = sm.sp4[t + 32 * s];
            a.x += v.x; a.y += v.y; a.z += v.z; a.w += v.w;
        }
        const int o = h * 128 + t * 4;
        g_y[r * 256 + o + 0] = a.x + bn2[o + 0];
        g_y[r * 256 + o + 1] = a.y + bn2[o + 1];
        g_y[r * 256 + o + 2] = a.z + bn2[o + 2];
        g_y[r * 256 + o + 3] = a.w + bn2[o + 3];
    }

    // peer must not exit while our DSMEM reads could be outstanding
    cluster.sync();

    gsync();

    // ================= Heads: blocks 0-3, head k = b =================
    if (b < 4) {
        const int k = b;
        float* agg = sm.ts;                 // reuse as agg[256]
        float* pfl = (float*)sm.sp4;
        {   // agg = mean over 64 rows of g_y
            const float4* Y = (const float4*)g_y;   // [64][64]
            const int c  = t & 63;
            const int rc = t >> 6;
            float4 a = make_float4(0.f, 0.f, 0.f, 0.f);
            #pragma unroll
            for (int j = 0; j < 16; j++) {
                float4 v = Y[(rc * 16 + j) * 64 + c];
                a.x += v.x; a.y += v.y; a.z += v.z; a.w += v.w;
            }
            sm.sp4[rc * 64 + c] = a;
        }
        __syncthreads();
        agg[t] = (pfl[t] + pfl[256 + t] + pfl[512 + t] + pfl[768 + t]) * (1.0f / 64.0f);
        __syncthreads();

        {   // z = agg @ Wh1[k]: 32 float4 d-groups x 8 c-slices
            const int dg   = t & 31;
            const int half = t >> 5;
            const float* Wb = Wh1 + k * 32768 + dg * 4;
            float4 acc = make_float4(0.f, 0.f, 0.f, 0.f);
            const int c0 = half * 32;
            #pragma unroll
            for (int c2 = c0; c2 < c0 + 32; c2++) {
                float  av = agg[c2];
                float4 wv = *(const float4*)(Wb + c2 * 128);
                acc.x = fmaf(av, wv.x, acc.x); acc.y = fmaf(av, wv.y, acc.y);
                acc.z = fmaf(av, wv.z, acc.z); acc.w = fmaf(av, wv.w, acc.w);
            }
            sm.sp4[t] = acc;
        }
        __syncthreads();
        if (t < 32) {
            float4 a = sm.sp4[t];
            #pragma unroll
            for (int s = 1; s < 8; s++) {
                float4 v = sm.sp4[t + 32 * s];
                a.x += v.x; a.y += v.y; a.z += v.z; a.w += v.w;
            }
            const int o = t * 4;
            sm.h1s[o + 0] = fmaxf(a.x + bh1[k * 128 + o + 0], 0.0f);
            sm.h1s[o + 1] = fmaxf(a.y + bh1[k * 128 + o + 1], 0.0f);
            sm.h1s[o + 2] = fmaxf(a.z + bh1[k * 128 + o + 2], 0.0f);
            sm.h1s[o + 3] = fmaxf(a.w + bh1[k * 128 + o + 3], 0.0f);
        }
        __syncthreads();
        if (t < 32) {
            float a = 0.0f;
            #pragma unroll
            for (int j = t; j < 128; j += 32)
                a = fmaf(sm.h1s[j], Wh2[k * 128 + j], a);
            #pragma unroll
            for (int off = 16; off; off >>= 1)
                a += __shfl_xor_sync(0xffffffffu, a, off);
            if (t == 0) out[k] = a + bh2[k];
        }
    }
}

extern "C" void kernel_launch(void* const* d_in, const int* in_sizes, int n_in,
                              void* d_out, int out_size)
{
    const float* positions = (const float*)d_in[0];
    const float* grid_pts  = (const float*)d_in[1];
    const float* W1  = (const float*)d_in[2];
    const float* b1  = (const float*)d_in[3];
    const float* W2  = (const float*)d_in[4];
    const float* b2  = (const float*)d_in[5];
    const float* W3  = (const float*)d_in[6];
    const float* b3  = (const float*)d_in[7];
    const float* Wn1 = (const float*)d_in[8];
    const float* bn1 = (const float*)d_in[9];
    const float* Wn2 = (const float*)d_in[10];
    const float* bn2 = (const float*)d_in[11];
    const float* Wh1 = (const float*)d_in[12];
    const float* bh1 = (const float*)d_in[13];
    const float* Wh2 = (const float*)d_in[14];
    const float* bh2 = (const float*)d_in[15];
    float* out = (float*)d_out;

    fused_kernel<<<NB, 256>>>(positions, grid_pts, W1, b1, W2, b2, W3, b3,
                              Wn1, bn1, Wn2, bn2, Wh1, bh1, Wh2, bh2, out);
}

// round 6
// speedup vs baseline: 3.0852x; 1.1629x over previous
#include <cuda_runtime.h>
#include <cuda_bf16.h>
#include <cooperative_groups.h>

namespace cg = cooperative_groups;

// ---------------------------------------------------------------------------
// Fused persistent kernel: 128 blocks = 32 clusters of 4, ONE grid sync.
// Only feat[0:64] is live (winner in -1..63) -> 500K-row MLP collapses to 64.
//
// Cluster cid = b>>2 owns rows r0=2*cid, r1=2*cid+1; rank q = b&3 owns
// column quarter [64q, 64q+64) of every 256-wide activation:
//   - winner table redundant; w0,w1 for the two rows
//   - MLP: L1,L2 redundant (cheap); L3 computes gf quarter (W3/4)
//   - all-gather gf quarters via DSMEM (cluster.sync)
//   - ts quarter = relu(gf @ Wn1[:,quarter] + bn1)   (Wn1/4)
//   - all-gather ts quarters via DSMEM (cluster.sync)
//   - y quarter = ts @ Wn2[:,quarter] + bn2 -> g_y   (Wn2/4)
// gsync
//   - blocks 0-3: agg = mean(g_y); head k=b -> out[k]
// Per-block weight bytes: 32K + 32K + 64K + 64K = 192KB (was 416KB).
// ---------------------------------------------------------------------------

#define G   64
#define NB  128

__device__ float g_y[G * 256];
__device__ unsigned long long g_ctr;   // monotonic across launches/replays

__device__ __forceinline__ void gsync()
{
    __syncthreads();
    if (threadIdx.x == 0) {
        __threadfence();
        unsigned long long ticket = atomicAdd(&g_ctr, 1ULL) + 1ULL;
        unsigned long long target = ((ticket + (NB - 1)) / NB) * (unsigned long long)NB;
        volatile unsigned long long* p = (volatile unsigned long long*)&g_ctr;
        while (*p < target) { }
        __threadfence();
    }
    __syncthreads();
}

struct SmemLayout {
    float  gf[2 * 256];     // full gf rows (own quarter + gathered)
    float  ts[2 * 256];     // full ts rows
    float4 sp4[512];        // chunk partials
    float  ps[192];
    float  gs[192];
    float  h1[2 * 64];
    float  h2[2 * 128];
    float  p[8];
    float  h1s[128];
    int    si[G];
    int    sw[4];
};

__global__ void __launch_bounds__(256, 1) __cluster_dims__(4, 1, 1)
fused_kernel(const float* __restrict__ pos, const float* __restrict__ gp,
             const float* __restrict__ W1,  const float* __restrict__ b1,
             const float* __restrict__ W2,  const float* __restrict__ b2,
             const float* __restrict__ W3,  const float* __restrict__ b3,
             const float* __restrict__ Wn1, const float* __restrict__ bn1,
             const float* __restrict__ Wn2, const float* __restrict__ bn2,
             const float* __restrict__ Wh1, const float* __restrict__ bh1,
             const float* __restrict__ Wh2, const float* __restrict__ bh2,
             float* __restrict__ out)
{
    __shared__ SmemLayout sm;
    const int b = blockIdx.x;
    const int t = threadIdx.x;
    cg::cluster_group cluster = cg::this_cluster();
    const int q   = b & 3;             // column quarter rank
    const int cid = b >> 2;            // cluster id
    const int r0  = cid * 2;
    const int r1  = r0 + 1;

    // ---- winner table (redundant per block) ----
    if (t < G * 3) { sm.ps[t] = pos[t]; sm.gs[t] = gp[t]; }
    __syncthreads();
    if (t < G) {
        const float px = sm.ps[t * 3], py = sm.ps[t * 3 + 1], pz = sm.ps[t * 3 + 2];
        float best = 3.4e38f; int bj = 0;
        #pragma unroll 4
        for (int j = 0; j < G; j++) {
            float dx = px - sm.gs[j * 3];
            float dy = py - sm.gs[j * 3 + 1];
            float dz = pz - sm.gs[j * 3 + 2];
            float d  = dx * dx + dy * dy + dz * dz;
            if (d < best) { best = d; bj = j; }     // argmin: first idx on ties
        }
        sm.si[t] = bj;
    }
    __syncthreads();
    if (t < G) {
        int c0 = (sm.si[t] == r0) ? t : -1;
        int c1 = (sm.si[t] == r1) ? t : -1;
        #pragma unroll
        for (int off = 16; off; off >>= 1) {
            c0 = max(c0, __shfl_xor_sync(0xffffffffu, c0, off));
            c1 = max(c1, __shfl_xor_sync(0xffffffffu, c1, off));
        }
        if ((t & 31) == 0) { sm.sw[t >> 5] = c0; sm.sw[2 + (t >> 5)] = c1; }
    }
    __syncthreads();
    const int w0 = max(sm.sw[0], sm.sw[1]);
    const int w1 = max(sm.sw[2], sm.sw[3]);

    // ---- MLP for both rows (clip(winner,0); zero-mask at gf) ----
    if (t < 3) {
        sm.p[t]     = pos[max(w0, 0) * 3 + t];
        sm.p[4 + t] = pos[max(w1, 0) * 3 + t];
    }
    __syncthreads();
    if (t < 64) {       // layer1: 3 -> 64, both rows
        float wa = W1[t], wb = W1[64 + t], wc = W1[128 + t], bb = b1[t];
        sm.h1[t]      = fmaxf(bb + sm.p[0] * wa + sm.p[1] * wb + sm.p[2] * wc, 0.0f);
        sm.h1[64 + t] = fmaxf(bb + sm.p[4] * wa + sm.p[5] * wb + sm.p[6] * wc, 0.0f);
    }
    __syncthreads();
    {   // layer2: 64 -> 128, both rows; 32 float4 col-groups, 8 chunks x 8 k
        const float4* W = (const float4*)W2;        // [64][32]
        const int c  = t & 31;
        const int ch = t >> 5;
        float4 a0 = make_float4(0.f, 0.f, 0.f, 0.f);
        float4 a1 = make_float4(0.f, 0.f, 0.f, 0.f);
        #pragma unroll
        for (int j = 0; j < 8; j++) {
            int k = ch * 8 + j;
            float4 wv = W[k * 32 + c];
            float  x0 = sm.h1[k], x1 = sm.h1[64 + k];
            a0.x = fmaf(x0, wv.x, a0.x); a0.y = fmaf(x0, wv.y, a0.y);
            a0.z = fmaf(x0, wv.z, a0.z); a0.w = fmaf(x0, wv.w, a0.w);
            a1.x = fmaf(x1, wv.x, a1.x); a1.y = fmaf(x1, wv.y, a1.y);
            a1.z = fmaf(x1, wv.z, a1.z); a1.w = fmaf(x1, wv.w, a1.w);
        }
        sm.sp4[ch * 32 + c]       = a0;
        sm.sp4[256 + ch * 32 + c] = a1;
    }
    __syncthreads();
    if (t < 64) {       // combine layer2: (row, col-group)
        const int row = t >> 5;
        const int c   = t & 31;
        float4 a = sm.sp4[row * 256 + c];
        #pragma unroll
        for (int s = 1; s < 8; s++) {
            float4 v = sm.sp4[row * 256 + s * 32 + c];
            a.x += v.x; a.y += v.y; a.z += v.z; a.w += v.w;
        }
        const int o = c * 4;
        float4 bb = *(const float4*)(b2 + o);
        float* dst = sm.h2 + row * 128 + o;
        dst[0] = fmaxf(a.x + bb.x, 0.0f);
        dst[1] = fmaxf(a.y + bb.y, 0.0f);
        dst[2] = fmaxf(a.z + bb.z, 0.0f);
        dst[3] = fmaxf(a.w + bb.w, 0.0f);
    }
    __syncthreads();
    {   // layer3 QUARTER: 64 cols of gf, both rows; 16 groups, 16 chunks x 8 k
        const float4* W = (const float4*)W3;        // [128][64]
        const int c  = t & 15;
        const int ch = t >> 4;
        float4 a0 = make_float4(0.f, 0.f, 0.f, 0.f);
        float4 a1 = make_float4(0.f, 0.f, 0.f, 0.f);
        #pragma unroll
        for (int j = 0; j < 8; j++) {
            int k = ch * 8 + j;
            float4 wv = W[k * 64 + q * 16 + c];
            float  x0 = sm.h2[k], x1 = sm.h2[128 + k];
            a0.x = fmaf(x0, wv.x, a0.x); a0.y = fmaf(x0, wv.y, a0.y);
            a0.z = fmaf(x0, wv.z, a0.z); a0.w = fmaf(x0, wv.w, a0.w);
            a1.x = fmaf(x1, wv.x, a1.x); a1.y = fmaf(x1, wv.y, a1.y);
            a1.z = fmaf(x1, wv.z, a1.z); a1.w = fmaf(x1, wv.w, a1.w);
        }
        sm.sp4[ch * 16 + c]       = a0;
        sm.sp4[256 + ch * 16 + c] = a1;
    }
    __syncthreads();
    if (t < 32) {       // combine gf quarter
        const int row = t >> 4;
        const int c   = t & 15;
        float4 a = sm.sp4[row * 256 + c];
        #pragma unroll
        for (int s = 1; s < 16; s++) {
            float4 v = sm.sp4[row * 256 + s * 16 + c];
            a.x += v.x; a.y += v.y; a.z += v.z; a.w += v.w;
        }
        const int o = q * 64 + c * 4;
        float4 bb = *(const float4*)(b3 + o);
        const int wr = row ? w1 : w0;
        const float m = (wr >= 0) ? 1.0f : 0.0f;
        float* dst = sm.gf + row * 256 + o;
        dst[0] = (a.x + bb.x) * m;
        dst[1] = (a.y + bb.y) * m;
        dst[2] = (a.z + bb.z) * m;
        dst[3] = (a.w + bb.w) * m;
    }
    __syncthreads();

    // ---- all-gather gf quarters via DSMEM ----
    cluster.sync();
    if (t < 96) {
        const int pid = t >> 5;                     // 0..2 peer slot
        const int qp  = pid + (pid >= q ? 1 : 0);   // actual peer rank
        const int idx = t & 31;
        const int row = idx >> 4;
        const int c   = idx & 15;
        const float* peer_gf = cluster.map_shared_rank((const float*)sm.gf, qp);
        const int o = row * 256 + qp * 64 + c * 4;
        *(float4*)(sm.gf + o) = *(const float4*)(peer_gf + o);
    }
    __syncthreads();

    // ---- ts quarter: relu(gf @ Wn1[:,quarter] + bn1), both rows ----
    {
        const float4* W = (const float4*)Wn1;       // [256][64]
        const int c  = t & 15;
        const int ch = t >> 4;                      // 16 chunks x 16 k
        float4 a0 = make_float4(0.f, 0.f, 0.f, 0.f);
        float4 a1 = make_float4(0.f, 0.f, 0.f, 0.f);
        #pragma unroll
        for (int j = 0; j < 16; j++) {
            int k = ch * 16 + j;
            float4 wv = W[k * 64 + q * 16 + c];
            float  x0 = sm.gf[k], x1 = sm.gf[256 + k];
            a0.x = fmaf(x0, wv.x, a0.x); a0.y = fmaf(x0, wv.y, a0.y);
            a0.z = fmaf(x0, wv.z, a0.z); a0.w = fmaf(x0, wv.w, a0.w);
            a1.x = fmaf(x1, wv.x, a1.x); a1.y = fmaf(x1, wv.y, a1.y);
            a1.z = fmaf(x1, wv.z, a1.z); a1.w = fmaf(x1, wv.w, a1.w);
        }
        sm.sp4[ch * 16 + c]       = a0;
        sm.sp4[256 + ch * 16 + c] = a1;
    }
    __syncthreads();
    if (t < 32) {
        const int row = t >> 4;
        const int c   = t & 15;
        float4 a = sm.sp4[row * 256 + c];
        #pragma unroll
        for (int s = 1; s < 16; s++) {
            float4 v = sm.sp4[row * 256 + s * 16 + c];
            a.x += v.x; a.y += v.y; a.z += v.z; a.w += v.w;
        }
        const int o = q * 64 + c * 4;
        float4 bb = *(const float4*)(bn1 + o);
        float* dst = sm.ts + row * 256 + o;
        dst[0] = fmaxf(a.x + bb.x, 0.0f);
        dst[1] = fmaxf(a.y + bb.y, 0.0f);
        dst[2] = fmaxf(a.z + bb.z, 0.0f);
        dst[3] = fmaxf(a.w + bb.w, 0.0f);
    }
    __syncthreads();

    // ---- all-gather ts quarters via DSMEM ----
    cluster.sync();
    if (t < 96) {
        const int pid = t >> 5;
        const int qp  = pid + (pid >= q ? 1 : 0);
        const int idx = t & 31;
        const int row = idx >> 4;
        const int c   = idx & 15;
        const float* peer_ts = cluster.map_shared_rank((const float*)sm.ts, qp);
        const int o = row * 256 + qp * 64 + c * 4;
        *(float4*)(sm.ts + o) = *(const float4*)(peer_ts + o);
    }
    __syncthreads();

    // ---- y quarter: ts @ Wn2[:,quarter] + bn2 -> g_y, both rows ----
    {
        const float4* W = (const float4*)Wn2;
        const int c  = t & 15;
        const int ch = t >> 4;
        float4 a0 = make_float4(0.f, 0.f, 0.f, 0.f);
        float4 a1 = make_float4(0.f, 0.f, 0.f, 0.f);
        #pragma unroll
        for (int j = 0; j < 16; j++) {
            int k = ch * 16 + j;
            float4 wv = W[k * 64 + q * 16 + c];
            float  x0 = sm.ts[k], x1 = sm.ts[256 + k];
            a0.x = fmaf(x0, wv.x, a0.x); a0.y = fmaf(x0, wv.y, a0.y);
            a0.z = fmaf(x0, wv.z, a0.z); a0.w = fmaf(x0, wv.w, a0.w);
            a1.x = fmaf(x1, wv.x, a1.x); a1.y = fmaf(x1, wv.y, a1.y);
            a1.z = fmaf(x1, wv.z, a1.z); a1.w = fmaf(x1, wv.w, a1.w);
        }
        sm.sp4[ch * 16 + c]       = a0;
        sm.sp4[256 + ch * 16 + c] = a1;
    }
    __syncthreads();
    if (t < 32) {
        const int row = t >> 4;
        const int c   = t & 15;
        float4 a = sm.sp4[row * 256 + c];
        #pragma unroll
        for (int s = 1; s < 16; s++) {
            float4 v = sm.sp4[row * 256 + s * 16 + c];
            a.x += v.x; a.y += v.y; a.z += v.z; a.w += v.w;
        }
        const int o = q * 64 + c * 4;
        float4 bb = *(const float4*)(bn2 + o);
        const int r = row ? r1 : r0;
        float4 v = make_float4(a.x + bb.x, a.y + bb.y, a.z + bb.z, a.w + bb.w);
        *(float4*)(g_y + r * 256 + o) = v;
    }

    gsync();

    // ================= Heads: blocks 0-3, head k = b =================
    if (b < 4) {
        const int k = b;
        float* agg = sm.ts;                 // reuse as agg[256]
        float* pfl = (float*)sm.sp4;
        {   // agg = mean over 64 rows of g_y
            const float4* Y = (const float4*)g_y;   // [64][64]
            const int c  = t & 63;
            const int rc = t >> 6;
            float4 a = make_float4(0.f, 0.f, 0.f, 0.f);
            #pragma unroll
            for (int j = 0; j < 16; j++) {
                float4 v = Y[(rc * 16 + j) * 64 + c];
                a.x += v.x; a.y += v.y; a.z += v.z; a.w += v.w;
            }
            sm.sp4[rc * 64 + c] = a;
        }
        __syncthreads();
        agg[t] = (pfl[t] + pfl[256 + t] + pfl[512 + t] + pfl[768 + t]) * (1.0f / 64.0f);
        __syncthreads();

        {   // z = agg @ Wh1[k]: 32 float4 d-groups x 8 c-slices
            const int dg   = t & 31;
            const int half = t >> 5;
            const float* Wb = Wh1 + k * 32768 + dg * 4;
            float4 acc = make_float4(0.f, 0.f, 0.f, 0.f);
            const int c0 = half * 32;
            #pragma unroll
            for (int c2 = c0; c2 < c0 + 32; c2++) {
                float  av = agg[c2];
                float4 wv = *(const float4*)(Wb + c2 * 128);
                acc.x = fmaf(av, wv.x, acc.x); acc.y = fmaf(av, wv.y, acc.y);
                acc.z = fmaf(av, wv.z, acc.z); acc.w = fmaf(av, wv.w, acc.w);
            }
            sm.sp4[t] = acc;
        }
        __syncthreads();
        if (t < 32) {
            float4 a = sm.sp4[t];
            #pragma unroll
            for (int s = 1; s < 8; s++) {
                float4 v = sm.sp4[t + 32 * s];
                a.x += v.x; a.y += v.y; a.z += v.z; a.w += v.w;
            }
            const int o = t * 4;
            sm.h1s[o + 0] = fmaxf(a.x + bh1[k * 128 + o + 0], 0.0f);
            sm.h1s[o + 1] = fmaxf(a.y + bh1[k * 128 + o + 1], 0.0f);
            sm.h1s[o + 2] = fmaxf(a.z + bh1[k * 128 + o + 2], 0.0f);
            sm.h1s[o + 3] = fmaxf(a.w + bh1[k * 128 + o + 3], 0.0f);
        }
        __syncthreads();
        if (t < 32) {
            float a = 0.0f;
            #pragma unroll
            for (int j = t; j < 128; j += 32)
                a = fmaf(sm.h1s[j], Wh2[k * 128 + j], a);
            #pragma unroll
            for (int off = 16; off; off >>= 1)
                a += __shfl_xor_sync(0xffffffffu, a, off);
            if (t == 0) out[k] = a + bh2[k];
        }
    }
}

extern "C" void kernel_launch(void* const* d_in, const int* in_sizes, int n_in,
                              void* d_out, int out_size)
{
    const float* positions = (const float*)d_in[0];
    const float* grid_pts  = (const float*)d_in[1];
    const float* W1  = (const float*)d_in[2];
    const float* b1  = (const float*)d_in[3];
    const float* W2  = (const float*)d_in[4];
    const float* b2  = (const float*)d_in[5];
    const float* W3  = (const float*)d_in[6];
    const float* b3  = (const float*)d_in[7];
    const float* Wn1 = (const float*)d_in[8];
    const float* bn1 = (const float*)d_in[9];
    const float* Wn2 = (const float*)d_in[10];
    const float* bn2 = (const float*)d_in[11];
    const float* Wh1 = (const float*)d_in[12];
    const float* bh1 = (const float*)d_in[13];
    const float* Wh2 = (const float*)d_in[14];
    const float* bh2 = (const float*)d_in[15];
    float* out = (float*)d_out;

    fused_kernel<<<NB, 256>>>(positions, grid_pts, W1, b1, W2, b2, W3, b3,
                              Wn1, bn1, Wn2, bn2, Wh1, bh1, Wh2, bh2, out);
}